// round 15
// baseline (speedup 1.0000x reference)
#include <cuda_runtime.h>
#include <cuda_bf16.h>
#include <cstdint>

// Shapes (fixed)
#define T_DIM   1024
#define N_BATCH 8
#define E_DIM   1024
#define H_HEADS 16
#define D_HEAD  64
#define B_HEADS 128
#define M_ROWS  8192
#define QKV_LD  3072
#define ROW_STRIDE 24576   // 8*3072

typedef __nv_bfloat16 bf16;

// ---------------- scratch (allocation-free) ----------------
__device__ bf16  g_qh [(size_t)M_ROWS * E_DIM];
__device__ bf16  g_ql [(size_t)M_ROWS * E_DIM];
__device__ bf16  g_wih[(size_t)QKV_LD * E_DIM];
__device__ bf16  g_wil[(size_t)QKV_LD * E_DIM];
__device__ bf16  g_woh[(size_t)E_DIM * E_DIM];
__device__ bf16  g_wol[(size_t)E_DIM * E_DIM];
__device__ bf16  g_qkvh[(size_t)M_ROWS * QKV_LD];
__device__ bf16  g_qkvl[(size_t)M_ROWS * QKV_LD];
__device__ bf16  g_vth[(size_t)N_BATCH * E_DIM * T_DIM];   // [n][d][s]
__device__ bf16  g_vtl[(size_t)N_BATCH * E_DIM * T_DIM];
__device__ bf16  g_eh [(size_t)B_HEADS * T_DIM * T_DIM];   // e hi plane
__device__ bf16  g_el [(size_t)B_HEADS * T_DIM * T_DIM];   // e lo plane
__device__ float g_linv[(size_t)B_HEADS * T_DIM];          // 1 / sum(e) per row
__device__ bf16  g_ch [(size_t)M_ROWS * E_DIM];
__device__ bf16  g_cl [(size_t)M_ROWS * E_DIM];

#define DEVFN __device__ __forceinline__

DEVFN uint32_t smem_u32(const void* p) {
    uint32_t a;
    asm("{ .reg .u64 t; cvta.to.shared.u64 t, %1; cvt.u32.u64 %0, t; }" : "=r"(a) : "l"(p));
    return a;
}
DEVFN void cpa16(uint32_t s, const void* g) {
    asm volatile("cp.async.cg.shared.global [%0], [%1], 16;" :: "r"(s), "l"(g));
}
DEVFN void cp_commit() { asm volatile("cp.async.commit_group;" ::: "memory"); }
template<int N> DEVFN void cp_wait() { asm volatile("cp.async.wait_group %0;" :: "n"(N) : "memory"); }
DEVFN void ldsm4(uint32_t* r, uint32_t a) {
    asm volatile("ldmatrix.sync.aligned.m8n8.x4.shared.b16 {%0,%1,%2,%3}, [%4];"
                 : "=r"(r[0]), "=r"(r[1]), "=r"(r[2]), "=r"(r[3]) : "r"(a));
}
DEVFN void mma16816(float* c, const uint32_t* a, const uint32_t* b) {
    asm volatile(
        "mma.sync.aligned.m16n8k16.row.col.f32.bf16.bf16.f32 "
        "{%0,%1,%2,%3}, {%4,%5,%6,%7}, {%8,%9}, {%0,%1,%2,%3};"
        : "+f"(c[0]), "+f"(c[1]), "+f"(c[2]), "+f"(c[3])
        : "r"(a[0]), "r"(a[1]), "r"(a[2]), "r"(a[3]), "r"(b[0]), "r"(b[1]));
}
DEVFN void split_store2(bf16* ph, bf16* pl, float a, float b) {
    bf16 h0 = __float2bfloat16(a), h1 = __float2bfloat16(b);
    bf16 l0 = __float2bfloat16(a - __bfloat162float(h0));
    bf16 l1 = __float2bfloat16(b - __bfloat162float(h1));
    *reinterpret_cast<__nv_bfloat162*>(ph) = __halves2bfloat162(h0, h1);
    *reinterpret_cast<__nv_bfloat162*>(pl) = __halves2bfloat162(l0, l1);
}

// ---------------------------------------------------------------------------
// Split-bf16 NT GEMM core, 128 threads / 4 warps of 64x64 each.
// CTA tile 128x128, BK=32, pitch-80 smem, double-buffered.
// ---------------------------------------------------------------------------
template<bool HAS_BIAS, bool SPLIT_OUT, bool EXP_OUT>
DEVFN void gemm_core4(const bf16* __restrict__ Ah, const bf16* __restrict__ Al, int lda,
                      const bf16* __restrict__ Bh, const bf16* __restrict__ Bl, int ldb,
                      const float* __restrict__ bias, float alpha,
                      float* __restrict__ C, bf16* __restrict__ Coh, bf16* __restrict__ Col,
                      int ldc, int K, int m0, int n0, char* smem)
{
    constexpr int PITCH = 80;
    constexpr int ASZ = 128 * PITCH;
    constexpr int BSZ = 128 * PITCH;
    constexpr int STAGE = 2 * ASZ + 2 * BSZ;
    const int tid = threadIdx.x;        // 0..127
    const uint32_t sbase = smem_u32(smem);

    auto load_stage = [&](int st, int kk) {
        uint32_t s0 = sbase + st * STAGE;
#pragma unroll
        for (int i = 0; i < 4; ++i) {
            int id = tid + i * 128;
            int row = id >> 2, ck = id & 3;
            uint32_t so = s0 + row * PITCH + ck * 16;
            size_t go = (size_t)(m0 + row) * lda + kk + ck * 8;
            cpa16(so, Ah + go);
            cpa16(so + ASZ, Al + go);
        }
#pragma unroll
        for (int i = 0; i < 4; ++i) {
            int id = tid + i * 128;
            int row = id >> 2, ck = id & 3;
            uint32_t so = s0 + 2 * ASZ + row * PITCH + ck * 16;
            size_t go = (size_t)(n0 + row) * ldb + kk + ck * 8;
            cpa16(so, Bh + go);
            cpa16(so + BSZ, Bl + go);
        }
    };

    const int lane = tid & 31, wid = tid >> 5;
    const int wm = wid & 1, wn = wid >> 1;
    const int lg = lane >> 3, lr = lane & 7;
    const int r0 = lane >> 2, c0 = (lane & 3) * 2;
    const uint32_t aLOff = (uint32_t)((wm * 64 + (lg & 1) * 8 + lr) * PITCH + (lg >> 1) * 16);
    const uint32_t bLOff = (uint32_t)((wn * 64 + (lg >> 1) * 8 + lr) * PITCH + (lg & 1) * 16);

    float acc[4][8][4];
#pragma unroll
    for (int i = 0; i < 4; i++)
#pragma unroll
        for (int j = 0; j < 8; j++) {
            acc[i][j][0] = 0.f; acc[i][j][1] = 0.f; acc[i][j][2] = 0.f; acc[i][j][3] = 0.f;
        }

    const int NC = K >> 5;
    load_stage(0, 0);
    cp_commit();

    for (int c = 0; c < NC; ++c) {
        if (c + 1 < NC) { load_stage((c + 1) & 1, (c + 1) * 32); cp_commit(); cp_wait<1>(); }
        else            { cp_wait<0>(); }
        __syncthreads();

        const uint32_t sA = sbase + (c & 1) * STAGE;
        const uint32_t sB = sA + 2 * ASZ;
#pragma unroll
        for (int ks = 0; ks < 2; ++ks) {
            uint32_t ah[4][4], al[4][4], bh[4][4], bl[4][4];
#pragma unroll
            for (int mt = 0; mt < 4; ++mt) {
                ldsm4(ah[mt], sA + aLOff + mt * 16 * PITCH + ks * 32);
                ldsm4(al[mt], sA + ASZ + aLOff + mt * 16 * PITCH + ks * 32);
            }
#pragma unroll
            for (int np = 0; np < 4; ++np) {
                ldsm4(bh[np], sB + bLOff + np * 16 * PITCH + ks * 32);
                ldsm4(bl[np], sB + BSZ + bLOff + np * 16 * PITCH + ks * 32);
            }
#pragma unroll
            for (int mt = 0; mt < 4; ++mt)
#pragma unroll
                for (int nt = 0; nt < 8; ++nt)
                    mma16816(acc[mt][nt], ah[mt], &bh[nt >> 1][(nt & 1) * 2]);
#pragma unroll
            for (int mt = 0; mt < 4; ++mt)
#pragma unroll
                for (int nt = 0; nt < 8; ++nt)
                    mma16816(acc[mt][nt], ah[mt], &bl[nt >> 1][(nt & 1) * 2]);
#pragma unroll
            for (int mt = 0; mt < 4; ++mt)
#pragma unroll
                for (int nt = 0; nt < 8; ++nt)
                    mma16816(acc[mt][nt], al[mt], &bh[nt >> 1][(nt & 1) * 2]);
        }
        __syncthreads();
    }

#pragma unroll
    for (int mt = 0; mt < 4; ++mt) {
#pragma unroll
        for (int nt = 0; nt < 8; ++nt) {
            int row = m0 + wm * 64 + mt * 16 + r0;
            int col = n0 + wn * 64 + nt * 8 + c0;
            float bx = HAS_BIAS ? bias[col] : 0.f;
            float by = HAS_BIAS ? bias[col + 1] : 0.f;
            float v00, v01, v10, v11;
            if constexpr (EXP_OUT) {
                v00 = __expf(alpha * acc[mt][nt][0]); v01 = __expf(alpha * acc[mt][nt][1]);
                v10 = __expf(alpha * acc[mt][nt][2]); v11 = __expf(alpha * acc[mt][nt][3]);
            } else {
                v00 = alpha * acc[mt][nt][0] + bx; v01 = alpha * acc[mt][nt][1] + by;
                v10 = alpha * acc[mt][nt][2] + bx; v11 = alpha * acc[mt][nt][3] + by;
            }
            if constexpr (SPLIT_OUT) {
                split_store2(Coh + (size_t)row * ldc + col, Col + (size_t)row * ldc + col, v00, v01);
                split_store2(Coh + (size_t)(row + 8) * ldc + col, Col + (size_t)(row + 8) * ldc + col, v10, v11);
            } else {
                *reinterpret_cast<float2*>(C + (size_t)row * ldc + col) = make_float2(v00, v01);
                *reinterpret_cast<float2*>(C + (size_t)(row + 8) * ldc + col) = make_float2(v10, v11);
            }
        }
    }
}

#define SMEM_128 (2 * (2 * 128 * 80 + 2 * 128 * 80))   // 81920

// 1) QKV projection -> (hi, lo) bf16 directly
__global__ __launch_bounds__(128, 2) void k_qkv(const float* __restrict__ bias) {
    extern __shared__ char smem[];
    gemm_core4<true, true, false>(g_qh, g_ql, E_DIM, g_wih, g_wil, E_DIM,
                                  bias, 1.f, nullptr, g_qkvh, g_qkvl, QKV_LD, E_DIM,
                                  blockIdx.y * 128, blockIdx.x * 128, smem);
}

// 2) e = exp(0.125 * Q K^T) -> (hi, lo) bf16 planes directly
__global__ __launch_bounds__(128, 2) void k_scores() {
    extern __shared__ char smem[];
    const int hb = blockIdx.z, n = hb >> 4, h = hb & 15;
    const bf16* Ah = g_qkvh + n * QKV_LD + h * D_HEAD;
    const bf16* Al = g_qkvl + n * QKV_LD + h * D_HEAD;
    bf16* Eh = g_eh + ((size_t)hb << 20);
    bf16* El = g_el + ((size_t)hb << 20);
    gemm_core4<false, true, true>(Ah, Al, ROW_STRIDE, Ah + E_DIM, Al + E_DIM, ROW_STRIDE,
                                  nullptr, 0.125f, nullptr, Eh, El, T_DIM, D_HEAD,
                                  blockIdx.y * 128, blockIdx.x * 128, smem);
}

// 3) out projection -> fp32 final output
__global__ __launch_bounds__(128, 2) void k_out(const float* __restrict__ bias, float* __restrict__ out) {
    extern __shared__ char smem[];
    gemm_core4<true, false, false>(g_ch, g_cl, E_DIM, g_woh, g_wol, E_DIM,
                                   bias, 1.f, out, nullptr, nullptr, E_DIM, E_DIM,
                                   blockIdx.y * 128, blockIdx.x * 128, smem);
}

// ---------------------------------------------------------------------------
// PV: ctx[t][h*64+d] = inv_l[t] * sum_s e[t][s] * vt[d][s]
// 8 warps of 32x32 (R12-proven core), A = e planes (bf16), B = vt planes.
// Epilogue: scale by inv_l, split-store ctx. 60KB smem -> 2 CTAs/SM.
// ---------------------------------------------------------------------------
#define SMEM_PV (2 * (2 * 128 * 80 + 2 * 64 * 80))    // 61440

__global__ __launch_bounds__(256) void k_pv() {
    extern __shared__ char smem[];
    constexpr int PITCH = 80;
    constexpr int ASZ = 128 * PITCH;
    constexpr int BSZ = 64 * PITCH;
    constexpr int STAGE = 2 * ASZ + 2 * BSZ;
    const int tid = threadIdx.x;
    const uint32_t sbase = smem_u32(smem);
    const int hb = blockIdx.y, n = hb >> 4, h = hb & 15;
    const int t0 = blockIdx.x * 128;

    const bf16* Ah = g_eh + ((size_t)hb << 20) + (size_t)t0 * 1024;
    const bf16* Al = g_el + ((size_t)hb << 20) + (size_t)t0 * 1024;
    const bf16* Bh = g_vth + ((size_t)n * E_DIM + h * D_HEAD) * T_DIM;
    const bf16* Bl = g_vtl + ((size_t)n * E_DIM + h * D_HEAD) * T_DIM;

    auto load_stage = [&](int st, int kk) {
        uint32_t s0 = sbase + st * STAGE;
#pragma unroll
        for (int i = 0; i < 2; ++i) {
            int id = tid + i * 256;
            int row = id >> 2, ck = id & 3;
            uint32_t so = s0 + row * PITCH + ck * 16;
            size_t go = (size_t)row * 1024 + kk + ck * 8;
            cpa16(so, Ah + go);
            cpa16(so + ASZ, Al + go);
        }
        {
            int row = tid >> 2, ck = tid & 3;   // 64 rows x 4 chunks
            uint32_t so = s0 + 2 * ASZ + row * PITCH + ck * 16;
            size_t go = (size_t)row * 1024 + kk + ck * 8;
            cpa16(so, Bh + go);
            cpa16(so + BSZ, Bl + go);
        }
    };

    const int lane = tid & 31, wid = tid >> 5;
    const int wm = wid & 3, wn = wid >> 2;          // 4x2 warp grid, 32x32 each
    const int lg = lane >> 3, lr = lane & 7;
    const int r0 = lane >> 2, c0 = (lane & 3) * 2;
    const uint32_t aLOff = (uint32_t)((wm * 32 + (lg & 1) * 8 + lr) * PITCH + (lg >> 1) * 16);
    const uint32_t bLOff = (uint32_t)((wn * 32 + (lg >> 1) * 8 + lr) * PITCH + (lg & 1) * 16);

    float acc[2][4][4];
#pragma unroll
    for (int i = 0; i < 2; i++)
#pragma unroll
        for (int j = 0; j < 4; j++) {
            acc[i][j][0] = 0.f; acc[i][j][1] = 0.f; acc[i][j][2] = 0.f; acc[i][j][3] = 0.f;
        }

    load_stage(0, 0);
    cp_commit();

    for (int c = 0; c < 32; ++c) {
        if (c + 1 < 32) { load_stage((c + 1) & 1, (c + 1) * 32); cp_commit(); cp_wait<1>(); }
        else            { cp_wait<0>(); }
        __syncthreads();

        const uint32_t sA = sbase + (c & 1) * STAGE;
        const uint32_t sB = sA + 2 * ASZ;
#pragma unroll
        for (int ks = 0; ks < 2; ++ks) {
            uint32_t ah[2][4], al[2][4], bh[2][4], bl[2][4];
#pragma unroll
            for (int mt = 0; mt < 2; ++mt) {
                ldsm4(ah[mt], sA + aLOff + mt * 16 * PITCH + ks * 32);
                ldsm4(al[mt], sA + ASZ + aLOff + mt * 16 * PITCH + ks * 32);
            }
#pragma unroll
            for (int np = 0; np < 2; ++np) {
                ldsm4(bh[np], sB + bLOff + np * 16 * PITCH + ks * 32);
                ldsm4(bl[np], sB + BSZ + bLOff + np * 16 * PITCH + ks * 32);
            }
#pragma unroll
            for (int mt = 0; mt < 2; ++mt)
#pragma unroll
                for (int nt = 0; nt < 4; ++nt) {
                    mma16816(acc[mt][nt], ah[mt], &bh[nt >> 1][(nt & 1) * 2]);
                    mma16816(acc[mt][nt], ah[mt], &bl[nt >> 1][(nt & 1) * 2]);
                    mma16816(acc[mt][nt], al[mt], &bh[nt >> 1][(nt & 1) * 2]);
                }
        }
        __syncthreads();
    }

    const float* linv = g_linv + ((size_t)hb << 10) + t0;
    bf16* Ch = g_ch + (size_t)n * E_DIM + h * D_HEAD;
    bf16* Cl = g_cl + (size_t)n * E_DIM + h * D_HEAD;
#pragma unroll
    for (int mt = 0; mt < 2; ++mt) {
#pragma unroll
        for (int nt = 0; nt < 4; ++nt) {
            int row = wm * 32 + mt * 16 + r0;
            int col = wn * 32 + nt * 8 + c0;
            float il0 = linv[row], il1 = linv[row + 8];
            size_t o0 = (size_t)(t0 + row) * (N_BATCH * E_DIM) + col;
            size_t o1 = (size_t)(t0 + row + 8) * (N_BATCH * E_DIM) + col;
            split_store2(Ch + o0, Cl + o0, acc[mt][nt][0] * il0, acc[mt][nt][1] * il0);
            split_store2(Ch + o1, Cl + o1, acc[mt][nt][2] * il1, acc[mt][nt][3] * il1);
        }
    }
}

// ---------------------------------------------------------------------------
// lavg: per (n,t) CTA reads e (hi+lo) for all 16 heads; computes l=sum(e),
// writes inv_l and the head-averaged probabilities (second output).
// ---------------------------------------------------------------------------
__global__ __launch_bounds__(256) void lavg_kernel(float* __restrict__ outAvg) {
    __shared__ float s_part[8][1024];
    const int bid = blockIdx.x;                 // n*1024 + t
    const int n = bid >> 10, t = bid & 1023;
    const int tid = threadIdx.x, lane = tid & 31, w = tid >> 5;

#pragma unroll
    for (int hh = 0; hh < 2; ++hh) {
        const int h = w + hh * 8;
        const int hb = n * 16 + h;
        const size_t base = ((size_t)hb << 20) + ((size_t)t << 10);
        const bf16* rh = g_eh + base;
        const bf16* rl = g_el + base;

        float4 v[8];
        float s = 0.f;
#pragma unroll
        for (int it = 0; it < 8; ++it) {
            const int col = it * 128 + lane * 4;
            union { uint2 u; __nv_bfloat162 b[2]; } H, L;
            H.u = *reinterpret_cast<const uint2*>(rh + col);
            L.u = *reinterpret_cast<const uint2*>(rl + col);
            float2 h0 = __bfloat1622float2(H.b[0]), h1 = __bfloat1622float2(H.b[1]);
            float2 l0 = __bfloat1622float2(L.b[0]), l1 = __bfloat1622float2(L.b[1]);
            v[it] = make_float4(h0.x + l0.x, h0.y + l0.y, h1.x + l1.x, h1.y + l1.y);
            s += (v[it].x + v[it].y) + (v[it].z + v[it].w);
        }
#pragma unroll
        for (int o = 16; o; o >>= 1) s += __shfl_xor_sync(0xffffffffu, s, o);
        const float inv = 1.0f / s;
        if (lane == 0) g_linv[((size_t)hb << 10) + t] = inv;

#pragma unroll
        for (int it = 0; it < 8; ++it) {
            const int col = it * 128 + lane * 4;
            if (hh == 0) {
                s_part[w][col + 0] = v[it].x * inv; s_part[w][col + 1] = v[it].y * inv;
                s_part[w][col + 2] = v[it].z * inv; s_part[w][col + 3] = v[it].w * inv;
            } else {
                s_part[w][col + 0] += v[it].x * inv; s_part[w][col + 1] += v[it].y * inv;
                s_part[w][col + 2] += v[it].z * inv; s_part[w][col + 3] += v[it].w * inv;
            }
        }
    }
    __syncthreads();

    const int col = tid * 4;
    float4 a = *reinterpret_cast<const float4*>(&s_part[0][col]);
#pragma unroll
    for (int p = 1; p < 8; ++p) {
        float4 b = *reinterpret_cast<const float4*>(&s_part[p][col]);
        a.x += b.x; a.y += b.y; a.z += b.z; a.w += b.w;
    }
    const float sc = 1.f / 16.f;
    *reinterpret_cast<float4*>(outAvg + ((size_t)bid << 10) + col) =
        make_float4(a.x * sc, a.y * sc, a.z * sc, a.w * sc);
}

// ---------------- split fp32 -> (hi, lo) bf16 (inputs only) ----------------
__global__ __launch_bounds__(256) void split_kernel(
    const float* __restrict__ x, bf16* __restrict__ h, bf16* __restrict__ l) {
    size_t i = (size_t)blockIdx.x * 256 + threadIdx.x;
    float4 v = reinterpret_cast<const float4*>(x)[i];
    bf16 h0 = __float2bfloat16(v.x), h1 = __float2bfloat16(v.y);
    bf16 h2 = __float2bfloat16(v.z), h3 = __float2bfloat16(v.w);
    bf16 l0 = __float2bfloat16(v.x - __bfloat162float(h0));
    bf16 l1 = __float2bfloat16(v.y - __bfloat162float(h1));
    bf16 l2 = __float2bfloat16(v.z - __bfloat162float(h2));
    bf16 l3 = __float2bfloat16(v.w - __bfloat162float(h3));
    union { __nv_bfloat162 b[2]; uint2 u; } H, L;
    H.b[0] = __halves2bfloat162(h0, h1); H.b[1] = __halves2bfloat162(h2, h3);
    L.b[0] = __halves2bfloat162(l0, l1); L.b[1] = __halves2bfloat162(l2, l3);
    *reinterpret_cast<uint2*>(h + i * 4) = H.u;
    *reinterpret_cast<uint2*>(l + i * 4) = L.u;
}

// ---------------- V transpose (pure bf16 copy of hi and lo planes) ----------------
__global__ __launch_bounds__(256) void vt_kernel() {
    __shared__ bf16 th[32][34];
    __shared__ bf16 tl[32][34];
    const int d0 = blockIdx.x * 32, s0 = blockIdx.y * 32, n = blockIdx.z;
    const int tx = threadIdx.x, ty = threadIdx.y;   // block (32, 8)
#pragma unroll
    for (int j = 0; j < 32; j += 8) {
        const size_t gi = ((size_t)(s0 + ty + j) * N_BATCH + n) * QKV_LD + 2 * E_DIM + d0 + tx;
        th[ty + j][tx] = g_qkvh[gi];
        tl[ty + j][tx] = g_qkvl[gi];
    }
    __syncthreads();
#pragma unroll
    for (int j = 0; j < 32; j += 8) {
        const int d = d0 + ty + j;
        const size_t o = ((size_t)n * E_DIM + d) * T_DIM + s0 + tx;
        g_vth[o] = th[tx][ty + j];
        g_vtl[o] = tl[tx][ty + j];
    }
}

// ---------------- host ----------------
extern "C" void kernel_launch(void* const* d_in, const int* in_sizes, int n_in,
                              void* d_out, int out_size) {
    (void)in_sizes; (void)n_in; (void)out_size;
    const float* query = (const float*)d_in[0];
    const float* in_w  = (const float*)d_in[3];
    const float* in_b  = (const float*)d_in[4];
    const float* out_w = (const float*)d_in[5];
    const float* out_b = (const float*)d_in[6];
    float* out = (float*)d_out;
    float* avg = out + (size_t)M_ROWS * E_DIM;

    void *qh, *ql, *wih, *wil, *woh, *wol;
    cudaGetSymbolAddress(&qh,  g_qh);  cudaGetSymbolAddress(&ql,  g_ql);
    cudaGetSymbolAddress(&wih, g_wih); cudaGetSymbolAddress(&wil, g_wil);
    cudaGetSymbolAddress(&woh, g_woh); cudaGetSymbolAddress(&wol, g_wol);

    cudaFuncSetAttribute(k_qkv,    cudaFuncAttributeMaxDynamicSharedMemorySize, SMEM_128);
    cudaFuncSetAttribute(k_scores, cudaFuncAttributeMaxDynamicSharedMemorySize, SMEM_128);
    cudaFuncSetAttribute(k_pv,     cudaFuncAttributeMaxDynamicSharedMemorySize, SMEM_PV);
    cudaFuncSetAttribute(k_out,    cudaFuncAttributeMaxDynamicSharedMemorySize, SMEM_128);

    // input splits
    split_kernel<<<(M_ROWS * E_DIM / 4) / 256, 256>>>(query, (bf16*)qh, (bf16*)ql);
    split_kernel<<<(QKV_LD * E_DIM / 4) / 256, 256>>>(in_w, (bf16*)wih, (bf16*)wil);
    split_kernel<<<(E_DIM * E_DIM / 4) / 256, 256>>>(out_w, (bf16*)woh, (bf16*)wol);

    // 1) QKV projection -> (qkvh, qkvl) directly
    k_qkv<<<dim3(QKV_LD / 128, M_ROWS / 128), 128, SMEM_128>>>(in_b);

    // 2) V transpose (bf16 planes)
    vt_kernel<<<dim3(E_DIM / 32, T_DIM / 32, N_BATCH), dim3(32, 8)>>>();

    // 3) e = exp(scores) -> (eh, el) bf16 planes
    k_scores<<<dim3(T_DIM / 128, T_DIM / 128, B_HEADS), 128, SMEM_128>>>();

    // 4) l + head-average (second output); writes inv_l
    lavg_kernel<<<N_BATCH * T_DIM, 256>>>(avg);

    // 5) PV (reads e planes + inv_l) -> (ch, cl)
    k_pv<<<dim3(T_DIM / 128, B_HEADS), 256, SMEM_PV>>>();

    // 6) out projection -> first output
    k_out<<<dim3(E_DIM / 128, M_ROWS / 128), 128, SMEM_128>>>(out_b, out);
}

// round 16
// speedup vs baseline: 1.1188x; 1.1188x over previous
#include <cuda_runtime.h>
#include <cuda_bf16.h>
#include <cstdint>

// Shapes (fixed)
#define T_DIM   1024
#define N_BATCH 8
#define E_DIM   1024
#define H_HEADS 16
#define D_HEAD  64
#define B_HEADS 128
#define M_ROWS  8192
#define QKV_LD  3072
#define ROW_STRIDE 24576   // 8*3072

typedef __nv_bfloat16 bf16;

// ---------------- scratch (allocation-free) ----------------
__device__ bf16  g_qh [(size_t)M_ROWS * E_DIM];
__device__ bf16  g_ql [(size_t)M_ROWS * E_DIM];
__device__ bf16  g_wih[(size_t)QKV_LD * E_DIM];
__device__ bf16  g_wil[(size_t)QKV_LD * E_DIM];
__device__ bf16  g_woh[(size_t)E_DIM * E_DIM];
__device__ bf16  g_wol[(size_t)E_DIM * E_DIM];
__device__ bf16  g_qkvh[(size_t)M_ROWS * QKV_LD];
__device__ bf16  g_qkvl[(size_t)M_ROWS * QKV_LD];
__device__ bf16  g_vth[(size_t)N_BATCH * E_DIM * T_DIM];   // [n][d][s]
__device__ bf16  g_vtl[(size_t)N_BATCH * E_DIM * T_DIM];
__device__ float g_attn[(size_t)B_HEADS * T_DIM * T_DIM];  // e = exp(score), fp32
__device__ float g_linv[(size_t)B_HEADS * T_DIM];          // 1 / sum(e) per row
__device__ bf16  g_ch [(size_t)M_ROWS * E_DIM];
__device__ bf16  g_cl [(size_t)M_ROWS * E_DIM];

#define DEVFN __device__ __forceinline__

DEVFN uint32_t smem_u32(const void* p) {
    uint32_t a;
    asm("{ .reg .u64 t; cvta.to.shared.u64 t, %1; cvt.u32.u64 %0, t; }" : "=r"(a) : "l"(p));
    return a;
}
DEVFN void cpa16(uint32_t s, const void* g) {
    asm volatile("cp.async.cg.shared.global [%0], [%1], 16;" :: "r"(s), "l"(g));
}
DEVFN void cp_commit() { asm volatile("cp.async.commit_group;" ::: "memory"); }
template<int N> DEVFN void cp_wait() { asm volatile("cp.async.wait_group %0;" :: "n"(N) : "memory"); }
DEVFN void ldsm4(uint32_t* r, uint32_t a) {
    asm volatile("ldmatrix.sync.aligned.m8n8.x4.shared.b16 {%0,%1,%2,%3}, [%4];"
                 : "=r"(r[0]), "=r"(r[1]), "=r"(r[2]), "=r"(r[3]) : "r"(a));
}
DEVFN void mma16816(float* c, const uint32_t* a, const uint32_t* b) {
    asm volatile(
        "mma.sync.aligned.m16n8k16.row.col.f32.bf16.bf16.f32 "
        "{%0,%1,%2,%3}, {%4,%5,%6,%7}, {%8,%9}, {%0,%1,%2,%3};"
        : "+f"(c[0]), "+f"(c[1]), "+f"(c[2]), "+f"(c[3])
        : "r"(a[0]), "r"(a[1]), "r"(a[2]), "r"(a[3]), "r"(b[0]), "r"(b[1]));
}
DEVFN void split_store2(bf16* ph, bf16* pl, float a, float b) {
    bf16 h0 = __float2bfloat16(a), h1 = __float2bfloat16(b);
    bf16 l0 = __float2bfloat16(a - __bfloat162float(h0));
    bf16 l1 = __float2bfloat16(b - __bfloat162float(h1));
    *reinterpret_cast<__nv_bfloat162*>(ph) = __halves2bfloat162(h0, h1);
    *reinterpret_cast<__nv_bfloat162*>(pl) = __halves2bfloat162(l0, l1);
}
DEVFN void cvt_split2(float2 f, uint32_t& hi, uint32_t& lo) {
    bf16 h0 = __float2bfloat16(f.x), h1 = __float2bfloat16(f.y);
    bf16 l0 = __float2bfloat16(f.x - __bfloat162float(h0));
    bf16 l1 = __float2bfloat16(f.y - __bfloat162float(h1));
    __nv_bfloat162 H = __halves2bfloat162(h0, h1);
    __nv_bfloat162 L = __halves2bfloat162(l0, l1);
    hi = *reinterpret_cast<uint32_t*>(&H);
    lo = *reinterpret_cast<uint32_t*>(&L);
}

// ---------------------------------------------------------------------------
// Split-bf16 NT GEMM core, 128 threads / 4 warps of 64x64 each.
// CTA tile 128x128, BK=32, pitch-80 smem, double-buffered.
// ---------------------------------------------------------------------------
template<bool HAS_BIAS, bool SPLIT_OUT, bool EXP_OUT>
DEVFN void gemm_core4(const bf16* __restrict__ Ah, const bf16* __restrict__ Al, int lda,
                      const bf16* __restrict__ Bh, const bf16* __restrict__ Bl, int ldb,
                      const float* __restrict__ bias, float alpha,
                      float* __restrict__ C, bf16* __restrict__ Coh, bf16* __restrict__ Col,
                      int ldc, int K, int m0, int n0, char* smem)
{
    constexpr int PITCH = 80;
    constexpr int ASZ = 128 * PITCH;
    constexpr int BSZ = 128 * PITCH;
    constexpr int STAGE = 2 * ASZ + 2 * BSZ;
    const int tid = threadIdx.x;        // 0..127
    const uint32_t sbase = smem_u32(smem);

    auto load_stage = [&](int st, int kk) {
        uint32_t s0 = sbase + st * STAGE;
#pragma unroll
        for (int i = 0; i < 4; ++i) {
            int id = tid + i * 128;
            int row = id >> 2, ck = id & 3;
            uint32_t so = s0 + row * PITCH + ck * 16;
            size_t go = (size_t)(m0 + row) * lda + kk + ck * 8;
            cpa16(so, Ah + go);
            cpa16(so + ASZ, Al + go);
        }
#pragma unroll
        for (int i = 0; i < 4; ++i) {
            int id = tid + i * 128;
            int row = id >> 2, ck = id & 3;
            uint32_t so = s0 + 2 * ASZ + row * PITCH + ck * 16;
            size_t go = (size_t)(n0 + row) * ldb + kk + ck * 8;
            cpa16(so, Bh + go);
            cpa16(so + BSZ, Bl + go);
        }
    };

    const int lane = tid & 31, wid = tid >> 5;
    const int wm = wid & 1, wn = wid >> 1;
    const int lg = lane >> 3, lr = lane & 7;
    const int r0 = lane >> 2, c0 = (lane & 3) * 2;
    const uint32_t aLOff = (uint32_t)((wm * 64 + (lg & 1) * 8 + lr) * PITCH + (lg >> 1) * 16);
    const uint32_t bLOff = (uint32_t)((wn * 64 + (lg >> 1) * 8 + lr) * PITCH + (lg & 1) * 16);

    float acc[4][8][4];
#pragma unroll
    for (int i = 0; i < 4; i++)
#pragma unroll
        for (int j = 0; j < 8; j++) {
            acc[i][j][0] = 0.f; acc[i][j][1] = 0.f; acc[i][j][2] = 0.f; acc[i][j][3] = 0.f;
        }

    const int NC = K >> 5;
    load_stage(0, 0);
    cp_commit();

    for (int c = 0; c < NC; ++c) {
        if (c + 1 < NC) { load_stage((c + 1) & 1, (c + 1) * 32); cp_commit(); cp_wait<1>(); }
        else            { cp_wait<0>(); }
        __syncthreads();

        const uint32_t sA = sbase + (c & 1) * STAGE;
        const uint32_t sB = sA + 2 * ASZ;
#pragma unroll
        for (int ks = 0; ks < 2; ++ks) {
            uint32_t ah[4][4], al[4][4], bh[4][4], bl[4][4];
#pragma unroll
            for (int mt = 0; mt < 4; ++mt) {
                ldsm4(ah[mt], sA + aLOff + mt * 16 * PITCH + ks * 32);
                ldsm4(al[mt], sA + ASZ + aLOff + mt * 16 * PITCH + ks * 32);
            }
#pragma unroll
            for (int np = 0; np < 4; ++np) {
                ldsm4(bh[np], sB + bLOff + np * 16 * PITCH + ks * 32);
                ldsm4(bl[np], sB + BSZ + bLOff + np * 16 * PITCH + ks * 32);
            }
#pragma unroll
            for (int mt = 0; mt < 4; ++mt)
#pragma unroll
                for (int nt = 0; nt < 8; ++nt)
                    mma16816(acc[mt][nt], ah[mt], &bh[nt >> 1][(nt & 1) * 2]);
#pragma unroll
            for (int mt = 0; mt < 4; ++mt)
#pragma unroll
                for (int nt = 0; nt < 8; ++nt)
                    mma16816(acc[mt][nt], ah[mt], &bl[nt >> 1][(nt & 1) * 2]);
#pragma unroll
            for (int mt = 0; mt < 4; ++mt)
#pragma unroll
                for (int nt = 0; nt < 8; ++nt)
                    mma16816(acc[mt][nt], al[mt], &bh[nt >> 1][(nt & 1) * 2]);
        }
        __syncthreads();
    }

#pragma unroll
    for (int mt = 0; mt < 4; ++mt) {
#pragma unroll
        for (int nt = 0; nt < 8; ++nt) {
            int row = m0 + wm * 64 + mt * 16 + r0;
            int col = n0 + wn * 64 + nt * 8 + c0;
            float bx = HAS_BIAS ? bias[col] : 0.f;
            float by = HAS_BIAS ? bias[col + 1] : 0.f;
            float v00, v01, v10, v11;
            if constexpr (EXP_OUT) {
                v00 = __expf(alpha * acc[mt][nt][0]); v01 = __expf(alpha * acc[mt][nt][1]);
                v10 = __expf(alpha * acc[mt][nt][2]); v11 = __expf(alpha * acc[mt][nt][3]);
            } else {
                v00 = alpha * acc[mt][nt][0] + bx; v01 = alpha * acc[mt][nt][1] + by;
                v10 = alpha * acc[mt][nt][2] + bx; v11 = alpha * acc[mt][nt][3] + by;
            }
            if constexpr (SPLIT_OUT) {
                split_store2(Coh + (size_t)row * ldc + col, Col + (size_t)row * ldc + col, v00, v01);
                split_store2(Coh + (size_t)(row + 8) * ldc + col, Col + (size_t)(row + 8) * ldc + col, v10, v11);
            } else {
                *reinterpret_cast<float2*>(C + (size_t)row * ldc + col) = make_float2(v00, v01);
                *reinterpret_cast<float2*>(C + (size_t)(row + 8) * ldc + col) = make_float2(v10, v11);
            }
        }
    }
}

#define SMEM_128 (2 * (2 * 128 * 80 + 2 * 128 * 80))   // 81920

// 1) QKV projection -> (hi, lo) bf16 directly
__global__ __launch_bounds__(128, 2) void k_qkv(const float* __restrict__ bias) {
    extern __shared__ char smem[];
    gemm_core4<true, true, false>(g_qh, g_ql, E_DIM, g_wih, g_wil, E_DIM,
                                  bias, 1.f, nullptr, g_qkvh, g_qkvl, QKV_LD, E_DIM,
                                  blockIdx.y * 128, blockIdx.x * 128, smem);
}

// 2) e = exp(0.125 * Q K^T) -> fp32
__global__ __launch_bounds__(128, 2) void k_scores() {
    extern __shared__ char smem[];
    const int hb = blockIdx.z, n = hb >> 4, h = hb & 15;
    const bf16* Ah = g_qkvh + n * QKV_LD + h * D_HEAD;
    const bf16* Al = g_qkvl + n * QKV_LD + h * D_HEAD;
    float* C = g_attn + ((size_t)hb << 20);
    gemm_core4<false, false, true>(Ah, Al, ROW_STRIDE, Ah + E_DIM, Al + E_DIM, ROW_STRIDE,
                                   nullptr, 0.125f, C, nullptr, nullptr, T_DIM, D_HEAD,
                                   blockIdx.y * 128, blockIdx.x * 128, smem);
}

// 3) out projection -> fp32 final output
__global__ __launch_bounds__(128, 2) void k_out(const float* __restrict__ bias, float* __restrict__ out) {
    extern __shared__ char smem[];
    gemm_core4<true, false, false>(g_ch, g_cl, E_DIM, g_woh, g_wol, E_DIM,
                                   bias, 1.f, out, nullptr, nullptr, E_DIM, E_DIM,
                                   blockIdx.y * 128, blockIdx.x * 128, smem);
}

// ---------------------------------------------------------------------------
// lavg: per (n,t) CTA reads fp32 e for all 16 heads; computes l=sum(e),
// writes inv_l, and the head-averaged probabilities (second output).
// ---------------------------------------------------------------------------
__global__ __launch_bounds__(256) void lavg_kernel(float* __restrict__ outAvg) {
    __shared__ float s_part[8][1024];
    const int bid = blockIdx.x;                 // n*1024 + t
    const int n = bid >> 10, t = bid & 1023;
    const int tid = threadIdx.x, lane = tid & 31, w = tid >> 5;

#pragma unroll
    for (int hh = 0; hh < 2; ++hh) {
        const int h = w + hh * 8;
        const int hb = n * 16 + h;
        const size_t base = ((size_t)hb << 20) + ((size_t)t << 10);
        const float* row = g_attn + base;

        float4 v[8];
        float s = 0.f;
#pragma unroll
        for (int it = 0; it < 8; ++it) {
            v[it] = *reinterpret_cast<const float4*>(row + it * 128 + lane * 4);
            s += (v[it].x + v[it].y) + (v[it].z + v[it].w);
        }
#pragma unroll
        for (int o = 16; o; o >>= 1) s += __shfl_xor_sync(0xffffffffu, s, o);
        const float inv = 1.0f / s;
        if (lane == 0) g_linv[((size_t)hb << 10) + t] = inv;

#pragma unroll
        for (int it = 0; it < 8; ++it) {
            const int col = it * 128 + lane * 4;
            if (hh == 0) {
                s_part[w][col + 0] = v[it].x * inv; s_part[w][col + 1] = v[it].y * inv;
                s_part[w][col + 2] = v[it].z * inv; s_part[w][col + 3] = v[it].w * inv;
            } else {
                s_part[w][col + 0] += v[it].x * inv; s_part[w][col + 1] += v[it].y * inv;
                s_part[w][col + 2] += v[it].z * inv; s_part[w][col + 3] += v[it].w * inv;
            }
        }
    }
    __syncthreads();

    const int col = tid * 4;
    float4 a = *reinterpret_cast<const float4*>(&s_part[0][col]);
#pragma unroll
    for (int p = 1; p < 8; ++p) {
        float4 b = *reinterpret_cast<const float4*>(&s_part[p][col]);
        a.x += b.x; a.y += b.y; a.z += b.z; a.w += b.w;
    }
    const float sc = 1.f / 16.f;
    *reinterpret_cast<float4*>(outAvg + ((size_t)bid << 10) + col) =
        make_float4(a.x * sc, a.y * sc, a.z * sc, a.w * sc);
}

// ---------------------------------------------------------------------------
// PV: ctx[t][h*64+d] = inv_l[t] * sum_s e[t][s] * vt[d][s]
// Stages fp32 e tile (pitch 144) + V hi/lo planes. A-fragments are loaded
// DIRECTLY from the fp32 tile via LDS.64 at mma fragment coordinates and
// converted to (hi,lo) bf16x2 in registers: no conversion smem stage, one
// less sync per chunk, 57KB smem.
// ---------------------------------------------------------------------------
#define PV_PITCH_E 144
#define PV_ESZ (128 * PV_PITCH_E)        // 18432
#define PV_VPL (64 * 80)                 // 5120
#define PV_VST (2 * PV_VPL)              // 10240
#define PV_VOFF (2 * PV_ESZ)             // 36864
#define PV_SMEM (PV_VOFF + 2 * PV_VST)   // 57344

__global__ __launch_bounds__(256) void k_pv() {
    extern __shared__ char smem[];
    const int tid = threadIdx.x, lane = tid & 31, wid = tid >> 5;
    const uint32_t sbase = smem_u32(smem);
    const int hb = blockIdx.y, n = hb >> 4, h = hb & 15;
    const int t0 = blockIdx.x * 128;

    const float* E  = g_attn + ((size_t)hb << 20) + (size_t)t0 * 1024;
    const bf16* Vh = g_vth + ((size_t)n * E_DIM + h * D_HEAD) * T_DIM;
    const bf16* Vl = g_vtl + ((size_t)n * E_DIM + h * D_HEAD) * T_DIM;

    auto load_stage = [&](int st, int c) {
        uint32_t r0a = sbase + st * PV_ESZ;
#pragma unroll
        for (int i = 0; i < 4; ++i) {               // e tile: 128 rows x 32 fp32
            int id = tid + i * 256;
            int row = id >> 3, ck = id & 7;
            cpa16(r0a + row * PV_PITCH_E + ck * 16, E + (size_t)row * 1024 + c * 32 + ck * 4);
        }
        uint32_t v0 = sbase + PV_VOFF + st * PV_VST;
        {
            int row = tid >> 2, ck = tid & 3;       // V planes: 64 rows x 32 bf16 each
            cpa16(v0 + row * 80 + ck * 16, Vh + (size_t)row * 1024 + c * 32 + ck * 8);
            cpa16(v0 + PV_VPL + row * 80 + ck * 16, Vl + (size_t)row * 1024 + c * 32 + ck * 8);
        }
    };

    const int wm = wid & 3, wn = wid >> 2;          // 4x2 warp grid, 32x32 tiles
    const int lg = lane >> 3, lr = lane & 7;
    const int r0 = lane >> 2, c0 = (lane & 3) * 2;
    const uint32_t bLOff = (uint32_t)((wn * 32 + (lg >> 1) * 8 + lr) * 80 + (lg & 1) * 16);

    float acc[2][4][4];
#pragma unroll
    for (int i = 0; i < 2; i++)
#pragma unroll
        for (int j = 0; j < 4; j++) {
            acc[i][j][0] = 0.f; acc[i][j][1] = 0.f; acc[i][j][2] = 0.f; acc[i][j][3] = 0.f;
        }

    load_stage(0, 0);
    cp_commit();

    for (int c = 0; c < 32; ++c) {
        if (c + 1 < 32) { load_stage((c + 1) & 1, c + 1); cp_commit(); cp_wait<1>(); }
        else            { cp_wait<0>(); }
        __syncthreads();

        const char* eb = smem + (c & 1) * PV_ESZ;
        const uint32_t sV = sbase + PV_VOFF + (c & 1) * PV_VST;
#pragma unroll
        for (int ks = 0; ks < 2; ++ks) {
            uint32_t ah[2][4], al[2][4], bh[2][4], bl[2][4];
#pragma unroll
            for (int mt = 0; mt < 2; ++mt) {
                const int rbase = wm * 32 + mt * 16 + r0;
                const int cb = ks * 16 + c0;
                float2 f0 = *reinterpret_cast<const float2*>(eb + (size_t)rbase * PV_PITCH_E + cb * 4);
                float2 f1 = *reinterpret_cast<const float2*>(eb + (size_t)(rbase + 8) * PV_PITCH_E + cb * 4);
                float2 f2 = *reinterpret_cast<const float2*>(eb + (size_t)rbase * PV_PITCH_E + (cb + 8) * 4);
                float2 f3 = *reinterpret_cast<const float2*>(eb + (size_t)(rbase + 8) * PV_PITCH_E + (cb + 8) * 4);
                cvt_split2(f0, ah[mt][0], al[mt][0]);
                cvt_split2(f1, ah[mt][1], al[mt][1]);
                cvt_split2(f2, ah[mt][2], al[mt][2]);
                cvt_split2(f3, ah[mt][3], al[mt][3]);
            }
#pragma unroll
            for (int np = 0; np < 2; ++np) {
                ldsm4(bh[np], sV + bLOff + np * 16 * 80 + ks * 32);
                ldsm4(bl[np], sV + PV_VPL + bLOff + np * 16 * 80 + ks * 32);
            }
#pragma unroll
            for (int mt = 0; mt < 2; ++mt)
#pragma unroll
                for (int nt = 0; nt < 4; ++nt) {
                    mma16816(acc[mt][nt], ah[mt], &bh[nt >> 1][(nt & 1) * 2]);
                    mma16816(acc[mt][nt], ah[mt], &bl[nt >> 1][(nt & 1) * 2]);
                    mma16816(acc[mt][nt], al[mt], &bh[nt >> 1][(nt & 1) * 2]);
                }
        }
        __syncthreads();
    }

    const float* linv = g_linv + ((size_t)hb << 10) + t0;
    bf16* Ch = g_ch + (size_t)n * E_DIM + h * D_HEAD;
    bf16* Cl = g_cl + (size_t)n * E_DIM + h * D_HEAD;
#pragma unroll
    for (int mt = 0; mt < 2; ++mt) {
#pragma unroll
        for (int nt = 0; nt < 4; ++nt) {
            int row = wm * 32 + mt * 16 + r0;
            int col = wn * 32 + nt * 8 + c0;
            float il0 = linv[row], il1 = linv[row + 8];
            size_t o0 = (size_t)(t0 + row) * (N_BATCH * E_DIM) + col;
            size_t o1 = (size_t)(t0 + row + 8) * (N_BATCH * E_DIM) + col;
            split_store2(Ch + o0, Cl + o0, acc[mt][nt][0] * il0, acc[mt][nt][1] * il0);
            split_store2(Ch + o1, Cl + o1, acc[mt][nt][2] * il1, acc[mt][nt][3] * il1);
        }
    }
}

// ---------------- split fp32 -> (hi, lo) bf16 (inputs only) ----------------
__global__ __launch_bounds__(256) void split_kernel(
    const float* __restrict__ x, bf16* __restrict__ h, bf16* __restrict__ l) {
    size_t i = (size_t)blockIdx.x * 256 + threadIdx.x;
    float4 v = reinterpret_cast<const float4*>(x)[i];
    bf16 h0 = __float2bfloat16(v.x), h1 = __float2bfloat16(v.y);
    bf16 h2 = __float2bfloat16(v.z), h3 = __float2bfloat16(v.w);
    bf16 l0 = __float2bfloat16(v.x - __bfloat162float(h0));
    bf16 l1 = __float2bfloat16(v.y - __bfloat162float(h1));
    bf16 l2 = __float2bfloat16(v.z - __bfloat162float(h2));
    bf16 l3 = __float2bfloat16(v.w - __bfloat162float(h3));
    union { __nv_bfloat162 b[2]; uint2 u; } H, L;
    H.b[0] = __halves2bfloat162(h0, h1); H.b[1] = __halves2bfloat162(h2, h3);
    L.b[0] = __halves2bfloat162(l0, l1); L.b[1] = __halves2bfloat162(l2, l3);
    *reinterpret_cast<uint2*>(h + i * 4) = H.u;
    *reinterpret_cast<uint2*>(l + i * 4) = L.u;
}

// ---------------- V transpose (pure bf16 copy of hi and lo planes) ----------------
__global__ __launch_bounds__(256) void vt_kernel() {
    __shared__ bf16 th[32][34];
    __shared__ bf16 tl[32][34];
    const int d0 = blockIdx.x * 32, s0 = blockIdx.y * 32, n = blockIdx.z;
    const int tx = threadIdx.x, ty = threadIdx.y;   // block (32, 8)
#pragma unroll
    for (int j = 0; j < 32; j += 8) {
        const size_t gi = ((size_t)(s0 + ty + j) * N_BATCH + n) * QKV_LD + 2 * E_DIM + d0 + tx;
        th[ty + j][tx] = g_qkvh[gi];
        tl[ty + j][tx] = g_qkvl[gi];
    }
    __syncthreads();
#pragma unroll
    for (int j = 0; j < 32; j += 8) {
        const int d = d0 + ty + j;
        const size_t o = ((size_t)n * E_DIM + d) * T_DIM + s0 + tx;
        g_vth[o] = th[tx][ty + j];
        g_vtl[o] = tl[tx][ty + j];
    }
}

// ---------------- host ----------------
extern "C" void kernel_launch(void* const* d_in, const int* in_sizes, int n_in,
                              void* d_out, int out_size) {
    (void)in_sizes; (void)n_in; (void)out_size;
    const float* query = (const float*)d_in[0];
    const float* in_w  = (const float*)d_in[3];
    const float* in_b  = (const float*)d_in[4];
    const float* out_w = (const float*)d_in[5];
    const float* out_b = (const float*)d_in[6];
    float* out = (float*)d_out;
    float* avg = out + (size_t)M_ROWS * E_DIM;

    void *qh, *ql, *wih, *wil, *woh, *wol;
    cudaGetSymbolAddress(&qh,  g_qh);  cudaGetSymbolAddress(&ql,  g_ql);
    cudaGetSymbolAddress(&wih, g_wih); cudaGetSymbolAddress(&wil, g_wil);
    cudaGetSymbolAddress(&woh, g_woh); cudaGetSymbolAddress(&wol, g_wol);

    cudaFuncSetAttribute(k_qkv,    cudaFuncAttributeMaxDynamicSharedMemorySize, SMEM_128);
    cudaFuncSetAttribute(k_scores, cudaFuncAttributeMaxDynamicSharedMemorySize, SMEM_128);
    cudaFuncSetAttribute(k_pv,     cudaFuncAttributeMaxDynamicSharedMemorySize, PV_SMEM);
    cudaFuncSetAttribute(k_out,    cudaFuncAttributeMaxDynamicSharedMemorySize, SMEM_128);

    // input splits
    split_kernel<<<(M_ROWS * E_DIM / 4) / 256, 256>>>(query, (bf16*)qh, (bf16*)ql);
    split_kernel<<<(QKV_LD * E_DIM / 4) / 256, 256>>>(in_w, (bf16*)wih, (bf16*)wil);
    split_kernel<<<(E_DIM * E_DIM / 4) / 256, 256>>>(out_w, (bf16*)woh, (bf16*)wol);

    // 1) QKV projection -> (qkvh, qkvl) directly
    k_qkv<<<dim3(QKV_LD / 128, M_ROWS / 128), 128, SMEM_128>>>(in_b);

    // 2) V transpose (bf16 planes)
    vt_kernel<<<dim3(E_DIM / 32, T_DIM / 32, N_BATCH), dim3(32, 8)>>>();

    // 3) e = exp(scores) -> fp32
    k_scores<<<dim3(T_DIM / 128, T_DIM / 128, B_HEADS), 128, SMEM_128>>>();

    // 4) l + head-average (second output); writes inv_l
    lavg_kernel<<<N_BATCH * T_DIM, 256>>>(avg);

    // 5) PV (reads fp32 e + inv_l, converts fragments in registers) -> (ch, cl)
    k_pv<<<dim3(T_DIM / 128, B_HEADS), 256, PV_SMEM>>>();

    // 6) out projection -> first output
    k_out<<<dim3(E_DIM / 128, M_ROWS / 128), 128, SMEM_128>>>(out_b, out);
}